// round 7
// baseline (speedup 1.0000x reference)
#include <cuda_runtime.h>

#define NN 500000
#define BB 4096
#define DD 256
#define DL 10
#define TH 768

typedef unsigned long long ull;

// ---------------- f32x2 packed-math helpers (sm_103a FFMA2 path) ----------------
__device__ __forceinline__ ull f2pack(float lo, float hi) {
    ull r; asm("mov.b64 %0, {%1, %2};" : "=l"(r) : "f"(lo), "f"(hi)); return r;
}
__device__ __forceinline__ void f2unpack(ull v, float& lo, float& hi) {
    asm("mov.b64 {%0, %1}, %2;" : "=f"(lo), "=f"(hi) : "l"(v));
}
__device__ __forceinline__ ull f2fma(ull a, ull b, ull c) {
    ull d; asm("fma.rn.f32x2 %0, %1, %2, %3;" : "=l"(d) : "l"(a), "l"(b), "l"(c)); return d;
}

// ---------------- device scratch (no allocation allowed) ----------------
__device__ int   d_segstart[BB + 1];
__device__ float d_c1[BB * DL];          // graph-half of layer1 + b_l1, per graph
__device__ float d_Sdiv[BB * DD];        // softmax-weighted mean of node feats per graph
__device__ float d_has[BB];              // 1 if segment nonempty else 0
__device__ float d_Wcomb[TH * DD];       // W_ih @ W_msg
__device__ float d_bmsgih[TH];           // W_ih @ b_msg
__device__ float d_gi[(size_t)BB * TH];
__device__ float d_gh[(size_t)BB * TH];

// ---------------- K1: segment boundaries (ids are sorted, int32) ----------------
__global__ void k_segstart(const int* __restrict__ seg) {
    int g = blockIdx.x * blockDim.x + threadIdx.x;
    if (g > BB) return;
    int lo = 0, hi = NN;
    while (lo < hi) {
        int mid = (lo + hi) >> 1;
        if (seg[mid] < g) lo = mid + 1; else hi = mid;
    }
    d_segstart[g] = lo;
}

// ---------------- K2: c1[g][j] = W_l1[j, :256] . relu(gf[g]) + b_l1[j] ----------------
__global__ void k_c1(const float* __restrict__ gf, const float* __restrict__ Wl1,
                     const float* __restrict__ bl1) {
    __shared__ float sc[DL];
    int g = blockIdx.x, t = threadIdx.x;
    if (t < DL) sc[t] = bl1[t];
    __syncthreads();
    float gv = fmaxf(gf[g * DD + t], 0.f);
#pragma unroll
    for (int j = 0; j < DL; j++) atomicAdd(&sc[j], Wl1[j * (2 * DD) + t] * gv);
    __syncthreads();
    if (t < DL) d_c1[g * DL + t] = sc[t];
}

// ---------------- K3: W_comb = W_ih @ W_msg  (768x256) ----------------
__global__ void k_wcomb(const float* __restrict__ Wih, const float* __restrict__ Wmsg) {
    __shared__ float wih_s[4][DD];
    int o0 = blockIdx.x * 4, t = threadIdx.x;
#pragma unroll
    for (int oo = 0; oo < 4; oo++) wih_s[oo][t] = Wih[(o0 + oo) * DD + t];
    __syncthreads();
    float a0 = 0.f, a1 = 0.f, a2 = 0.f, a3 = 0.f;
    for (int m = 0; m < DD; m++) {
        float wm = Wmsg[m * DD + t];
        a0 = fmaf(wih_s[0][m], wm, a0);
        a1 = fmaf(wih_s[1][m], wm, a1);
        a2 = fmaf(wih_s[2][m], wm, a2);
        a3 = fmaf(wih_s[3][m], wm, a3);
    }
    d_Wcomb[(o0 + 0) * DD + t] = a0;
    d_Wcomb[(o0 + 1) * DD + t] = a1;
    d_Wcomb[(o0 + 2) * DD + t] = a2;
    d_Wcomb[(o0 + 3) * DD + t] = a3;
}

// ---------------- K3b: bmsg_ih[o] = W_ih[o] . b_msg ----------------
__global__ void k_bmsgih(const float* __restrict__ Wih, const float* __restrict__ bmsg) {
    __shared__ float s;
    int o = blockIdx.x, t = threadIdx.x;
    if (t == 0) s = 0.f;
    __syncthreads();
    float v = Wih[o * DD + t] * bmsg[t];
#pragma unroll
    for (int off = 16; off; off >>= 1) v += __shfl_xor_sync(0xffffffffu, v, off);
    if ((t & 31) == 0) atomicAdd(&s, v);
    __syncthreads();
    if (t == 0) d_bmsgih[o] = s;
}

// ---------------- K4: fused attention + weighted segment mean (lane = node) ----------------
// Block = 4 warps = 1 graph. Each warp stages a 32-node tile in smem
// (row stride 260 floats: conflict-free for both row-wise and column-wise
// float4/ulonglong2 access), then:
//   phase 1: lane n computes node n's 10-logit dot serially over k (f32x2,
//            W broadcast from smem) -> lg -> w = exp(leaky(...)). NO shuffles.
//   phase 2: lane owns 8 features; per node: shfl-broadcast w + 2 LDS + 4 f2fma.
// Z accumulated per-lane; one butterfly per warp at the very end.
extern __shared__ float dynsmem[];   // [10*260 W] + [4 warps][32*260 X]
__global__ void __launch_bounds__(128) k_attn(const float* __restrict__ xf,
                                              const float* __restrict__ Wl1,
                                              const float* __restrict__ Wl2,
                                              const float* __restrict__ bl2) {
    __shared__ float c_s[DL];
    __shared__ float w2_s[DL];
    __shared__ float s_Z[4];
    __shared__ float4 s_acc[4][64];
    int tid = threadIdx.x;
    int wo = tid >> 5, lane = tid & 31;
    int g = blockIdx.x;

    float* Ws = dynsmem;                              // [10][260]
    float* Xw = dynsmem + DL * 260 + wo * (32 * 260); // this warp's [32][260]

    for (int i = tid; i < DL * DD; i += 128) {
        int j = i >> 8, f = i & 255;
        Ws[j * 260 + f] = Wl1[j * (2 * DD) + DD + f];
    }
    if (tid < DL) { c_s[tid] = d_c1[g * DL + tid]; w2_s[tid] = Wl2[tid]; }
    __syncthreads();

    float c1r[DL], w2r[DL];
#pragma unroll
    for (int j = 0; j < DL; j++) { c1r[j] = c_s[j]; w2r[j] = w2_s[j]; }
    float b2v = bl2[0];

    int i0 = d_segstart[g], i1 = d_segstart[g + 1];

    ull accA = 0ull, accB = 0ull, accC = 0ull, accD = 0ull;
    float zacc = 0.f;

    for (int base = i0 + wo * 32; base < i1; base += 128) {
        int cnt = min(32, i1 - base);

        // ---- load tile: coalesced, batched 8 nodes (16 LDG in flight) ----
        for (int n0 = 0; n0 < cnt; n0 += 8) {
            int m = min(8, cnt - n0);
            float4 va[8], vb[8];
#pragma unroll
            for (int n = 0; n < 8; n++) {
                if (n < m) {
                    const float4* rp = (const float4*)(xf + (size_t)(base + n0 + n) * DD);
                    va[n] = rp[lane]; vb[n] = rp[32 + lane];
                }
            }
#pragma unroll
            for (int n = 0; n < 8; n++) {
                if (n < m) {
                    *(float4*)&Xw[(n0 + n) * 260 + lane * 4] = va[n];
                    *(float4*)&Xw[(n0 + n) * 260 + 128 + lane * 4] = vb[n];
                }
            }
        }
        __syncwarp();

        // ---- phase 1: lane = node, serial dot over k, 20 independent f2 chains ----
        ull lgp[DL];
#pragma unroll
        for (int j = 0; j < DL; j++) lgp[j] = 0ull;
        const float* xrow = &Xw[lane * 260];
#pragma unroll 4
        for (int k4 = 0; k4 < 64; k4++) {
            ulonglong2 xv = *(const ulonglong2*)(xrow + k4 * 4);
#pragma unroll
            for (int j = 0; j < DL; j++) {
                ulonglong2 wv = *(const ulonglong2*)(Ws + j * 260 + k4 * 4);
                lgp[j] = f2fma(xv.x, wv.x, lgp[j]);
                lgp[j] = f2fma(xv.y, wv.y, lgp[j]);
            }
        }
        float lg = b2v;
#pragma unroll
        for (int j = 0; j < DL; j++) {
            float lo, hi; f2unpack(lgp[j], lo, hi);
            float h = c1r[j] + (lo + hi);
            h = (h > 0.f) ? h : 0.01f * h;
            lg = fmaf(w2r[j], h, lg);
        }
        lg = (lg > 0.f) ? lg : 0.01f * lg;
        float w = (lane < cnt) ? __expf(lg) : 0.f;   // logits O(0.2): no max-sub
        zacc += w;

        // ---- phase 2: lane owns 8 features, accumulate over the tile's nodes ----
        for (int n = 0; n < cnt; n++) {
            float wn = __shfl_sync(0xffffffffu, w, n);
            ulonglong2 x1 = *(const ulonglong2*)&Xw[n * 260 + lane * 4];
            ulonglong2 x2 = *(const ulonglong2*)&Xw[n * 260 + 128 + lane * 4];
            ull wd = f2pack(wn, wn);
            accA = f2fma(wd, x1.x, accA);
            accB = f2fma(wd, x1.y, accB);
            accC = f2fma(wd, x2.x, accC);
            accD = f2fma(wd, x2.y, accD);
        }
        __syncwarp();   // WAR: everyone done reading Xw before next tile's stores
    }

    // warp Z reduce (once)
#pragma unroll
    for (int off = 16; off; off >>= 1) zacc += __shfl_xor_sync(0xffffffffu, zacc, off);

    // combine 4 warps
    float a0f, a1f, a2f, a3f, a4f, a5f, a6f, a7f;
    f2unpack(accA, a0f, a1f); f2unpack(accB, a2f, a3f);
    f2unpack(accC, a4f, a5f); f2unpack(accD, a6f, a7f);
    if (lane == 0) s_Z[wo] = zacc;
    s_acc[wo][lane]      = make_float4(a0f, a1f, a2f, a3f);
    s_acc[wo][32 + lane] = make_float4(a4f, a5f, a6f, a7f);
    __syncthreads();
    if (tid < 64) {
        float Zt = s_Z[0] + s_Z[1] + s_Z[2] + s_Z[3];
        float invZ = (i1 > i0) ? (1.f / Zt) : 0.f;
        float4 v0 = s_acc[0][tid], v1 = s_acc[1][tid], v2 = s_acc[2][tid], v3 = s_acc[3][tid];
        float4 o;
        o.x = (v0.x + v1.x + v2.x + v3.x) * invZ;
        o.y = (v0.y + v1.y + v2.y + v3.y) * invZ;
        o.z = (v0.z + v1.z + v2.z + v3.z) * invZ;
        o.w = (v0.w + v1.w + v2.w + v3.w) * invZ;
        ((float4*)(d_Sdiv + (size_t)g * DD))[tid] = o;
        if (tid == 0) d_has[g] = (i1 > i0) ? 1.f : 0.f;
    }
}

#define ATTN_SMEM ((DL * 260 + 4 * 32 * 260) * (int)sizeof(float))

// ---------------- K5: SGEMM  C[4096x768] = A[4096x256] * B[768x256]^T + bias ----------------
// 128x128 tile, 8x8 per thread, 256 threads; inner product in f32x2 (FFMA2).
__global__ void __launch_bounds__(256) k_gemm(int mode, const float* __restrict__ Aparam,
                                              const float* __restrict__ Bparam,
                                              const float* __restrict__ bias) {
    const float* A  = mode ? Aparam : d_Sdiv;
    const float* Bw = mode ? Bparam : d_Wcomb;
    float* C = mode ? d_gh : d_gi;

    __shared__ float As[8][128];
    __shared__ float Bs[8][128];
    int bm = blockIdx.y * 128, bn = blockIdx.x * 128;
    int tid = threadIdx.x;
    int lr = tid >> 1, lc = (tid & 1) * 4;   // load: 128 rows x 8 k
    int tx = tid & 15, ty = tid >> 4;        // 16x16 threads, 8x8 each

    ull acc2[8][4];                          // [m][n-pair]
#pragma unroll
    for (int i = 0; i < 8; i++)
#pragma unroll
        for (int j = 0; j < 4; j++) acc2[i][j] = 0ull;

    float4 av = *(const float4*)(A + (size_t)(bm + lr) * DD + lc);
    float4 bv = *(const float4*)(Bw + (size_t)(bn + lr) * DD + lc);

    for (int k0 = 0; k0 < DD; k0 += 8) {
        As[lc + 0][lr] = av.x; As[lc + 1][lr] = av.y;
        As[lc + 2][lr] = av.z; As[lc + 3][lr] = av.w;
        Bs[lc + 0][lr] = bv.x; Bs[lc + 1][lr] = bv.y;
        Bs[lc + 2][lr] = bv.z; Bs[lc + 3][lr] = bv.w;
        __syncthreads();
        if (k0 + 8 < DD) {
            av = *(const float4*)(A + (size_t)(bm + lr) * DD + k0 + 8 + lc);
            bv = *(const float4*)(Bw + (size_t)(bn + lr) * DD + k0 + 8 + lc);
        }
#pragma unroll
        for (int k = 0; k < 8; k++) {
            float4 ap = *(const float4*)&As[k][ty * 4];
            float4 aq = *(const float4*)&As[k][64 + ty * 4];
            ulonglong2 bp = *(const ulonglong2*)&Bs[k][tx * 4];
            ulonglong2 bq = *(const ulonglong2*)&Bs[k][64 + tx * 4];
            ull ad[8];
            ad[0] = f2pack(ap.x, ap.x); ad[1] = f2pack(ap.y, ap.y);
            ad[2] = f2pack(ap.z, ap.z); ad[3] = f2pack(ap.w, ap.w);
            ad[4] = f2pack(aq.x, aq.x); ad[5] = f2pack(aq.y, aq.y);
            ad[6] = f2pack(aq.z, aq.z); ad[7] = f2pack(aq.w, aq.w);
#pragma unroll
            for (int i = 0; i < 8; i++) {
                acc2[i][0] = f2fma(ad[i], bp.x, acc2[i][0]);
                acc2[i][1] = f2fma(ad[i], bp.y, acc2[i][1]);
                acc2[i][2] = f2fma(ad[i], bq.x, acc2[i][2]);
                acc2[i][3] = f2fma(ad[i], bq.y, acc2[i][3]);
            }
        }
        __syncthreads();
    }

#pragma unroll
    for (int i = 0; i < 8; i++) {
        int m = bm + ((i < 4) ? (ty * 4 + i) : (64 + ty * 4 + (i - 4)));
        float hv = mode ? 0.f : d_has[m];
#pragma unroll
        for (int jh = 0; jh < 2; jh++) {
            int n0 = bn + jh * 64 + tx * 4;
            float c0, c1, c2, c3;
            f2unpack(acc2[i][jh * 2 + 0], c0, c1);
            f2unpack(acc2[i][jh * 2 + 1], c2, c3);
            float4 o;
            o.x = c0 + bias[n0 + 0] + (mode ? 0.f : hv * d_bmsgih[n0 + 0]);
            o.y = c1 + bias[n0 + 1] + (mode ? 0.f : hv * d_bmsgih[n0 + 1]);
            o.z = c2 + bias[n0 + 2] + (mode ? 0.f : hv * d_bmsgih[n0 + 2]);
            o.w = c3 + bias[n0 + 3] + (mode ? 0.f : hv * d_bmsgih[n0 + 3]);
            *(float4*)(C + (size_t)m * TH + n0) = o;
        }
    }
}

// ---------------- K6: GRU gate combine (float4) ----------------
__global__ void k_gates(const float* __restrict__ gf, float* __restrict__ out) {
    int idx = blockIdx.x * blockDim.x + threadIdx.x;   // over BB*DD/4
    int g = idx >> 6, f4 = idx & 63;
    const float4* gi = (const float4*)(d_gi + (size_t)g * TH);
    const float4* gh = (const float4*)(d_gh + (size_t)g * TH);
    float4 ir = gi[f4],      iz = gi[64 + f4],  in_ = gi[128 + f4];
    float4 hr = gh[f4],      hz = gh[64 + f4],  hn  = gh[128 + f4];
    float4 gfv = ((const float4*)gf)[idx];
    float4 o;
    {
        float r = 1.f / (1.f + __expf(-(ir.x + hr.x)));
        float z = 1.f / (1.f + __expf(-(iz.x + hz.x)));
        float n = tanhf(in_.x + r * hn.x);
        o.x = (1.f - z) * n + z * gfv.x;
    }
    {
        float r = 1.f / (1.f + __expf(-(ir.y + hr.y)));
        float z = 1.f / (1.f + __expf(-(iz.y + hz.y)));
        float n = tanhf(in_.y + r * hn.y);
        o.y = (1.f - z) * n + z * gfv.y;
    }
    {
        float r = 1.f / (1.f + __expf(-(ir.z + hr.z)));
        float z = 1.f / (1.f + __expf(-(iz.z + hz.z)));
        float n = tanhf(in_.z + r * hn.z);
        o.z = (1.f - z) * n + z * gfv.z;
    }
    {
        float r = 1.f / (1.f + __expf(-(ir.w + hr.w)));
        float z = 1.f / (1.f + __expf(-(iz.w + hz.w)));
        float n = tanhf(in_.w + r * hn.w);
        o.w = (1.f - z) * n + z * gfv.w;
    }
    ((float4*)out)[idx] = o;
}

// ---------------- launch ----------------
extern "C" void kernel_launch(void* const* d_in, const int* in_sizes, int n_in,
                              void* d_out, int out_size) {
    const float* node = (const float*)d_in[0];
    const float* gf   = (const float*)d_in[1];
    const int*   seg  = (const int*)d_in[2];     // JAX coerces int64 -> int32 (x64 disabled)
    const float* Wmsg = (const float*)d_in[3];
    const float* bmsg = (const float*)d_in[4];
    const float* Wl1  = (const float*)d_in[5];
    const float* bl1  = (const float*)d_in[6];
    const float* Wl2  = (const float*)d_in[7];
    const float* bl2  = (const float*)d_in[8];
    const float* Wih  = (const float*)d_in[9];
    const float* Whh  = (const float*)d_in[10];
    const float* bih  = (const float*)d_in[11];
    const float* bhh  = (const float*)d_in[12];
    float* out = (float*)d_out;

    cudaFuncSetAttribute(k_attn, cudaFuncAttributeMaxDynamicSharedMemorySize, ATTN_SMEM);

    k_segstart<<<(BB + 1 + 255) / 256, 256>>>(seg);
    k_c1<<<BB, 256>>>(gf, Wl1, bl1);
    k_wcomb<<<TH / 4, 256>>>(Wih, Wmsg);
    k_bmsgih<<<TH, 256>>>(Wih, bmsg);
    k_attn<<<BB, 128, ATTN_SMEM>>>(node, Wl1, Wl2, bl2);
    dim3 gg(TH / 128, BB / 128);
    k_gemm<<<gg, 256>>>(0, nullptr, nullptr, bih);
    k_gemm<<<gg, 256>>>(1, gf, Whh, bhh);
    k_gates<<<(BB * DD / 4) / 256, 256>>>(gf, out);
}